// round 13
// baseline (speedup 1.0000x reference)
#include <cuda_runtime.h>
#include <cstdint>

// Problem constants (fixed by the dataset: V=8192 vertices, E=40000 tets)
#define V 8192
#define E 40000
#define E_BLOCKS ((E + 255) / 256)
#define ROWS_PER_TILE 4
#define MV_BLOCKS (V / ROWS_PER_TILE)   // 2048
#define MV_ITERS 8                      // 8192 cols / (256 thr * 4 floats)

// Scratch (device globals — no allocations allowed). 16B-aligned for float4 LDG.
__device__ __align__(16) float g_dx[V];
__device__ __align__(16) float g_dy[V];
__device__ __align__(16) float g_dz[V];
__device__ double g_kin_accum;    // sum_i delta_i . (M delta)_i   (atomic)
__device__ double g_el_accum;     // sum_e psi_e * measure_e       (atomic)
__device__ unsigned int g_done;   // matvec block completion counter

// ---------------------------------------------------------------------------
// Kernel 1 (fused prologue): elastic energy per element + delta computation.
// elements is int32 on device (JAX x64 disabled); clamped defensively.
// ---------------------------------------------------------------------------
__global__ __launch_bounds__(256) void prologue_kernel(
    const float* __restrict__ next_pos,
    const float* __restrict__ pos,
    const float* __restrict__ vel,
    const float* __restrict__ ext,
    const float* __restrict__ ts_ptr,
    const int* __restrict__ elems,
    const float* __restrict__ poly,
    const float* __restrict__ measure,
    const float* __restrict__ lam,
    const float* __restrict__ mu)
{
    int gid = blockIdx.x * blockDim.x + threadIdx.x;

    if (gid == 0) {
        g_kin_accum = 0.0;
        g_el_accum  = 0.0;
        g_done      = 0u;
    }

    // --- delta part (first V threads) ---
    if (gid < V) {
        float dt  = ts_ptr[0];
        float dt2 = dt * dt;
        int b = gid * 3;
        g_dx[gid] = next_pos[b + 0] - (pos[b + 0] + vel[b + 0] * dt + ext[b + 0] * dt2);
        g_dy[gid] = next_pos[b + 1] - (pos[b + 1] + vel[b + 1] * dt + ext[b + 1] * dt2);
        g_dz[gid] = next_pos[b + 2] - (pos[b + 2] + vel[b + 2] * dt + ext[b + 2] * dt2);
    }

    // --- elastic part ---
    float val = 0.f;
    if (gid < E) {
        int e = gid;
        float F00 = 0.f, F01 = 0.f, F02 = 0.f;
        float F10 = 0.f, F11 = 0.f, F12 = 0.f;
        float F20 = 0.f, F21 = 0.f, F22 = 0.f;
        const int4 ev = reinterpret_cast<const int4*>(elems)[e];
        int vidx[4] = { ev.x, ev.y, ev.z, ev.w };
        const float4* __restrict__ pl4 = reinterpret_cast<const float4*>(poly) + (size_t)e * 4;
#pragma unroll
        for (int f = 0; f < 4; ++f) {
            int vi = vidx[f];
            vi = vi < 0 ? 0 : (vi >= V ? V - 1 : vi);   // defensive clamp
            const float* p = next_pos + (size_t)vi * 3;
            float px = p[0], py = p[1], pz = p[2];
            float4 pl = pl4[f];
            float p0 = pl.x, p1 = pl.y, p2 = pl.z;
            F00 += px * p0; F01 += px * p1; F02 += px * p2;
            F10 += py * p0; F11 += py * p1; F12 += py * p2;
            F20 += pz * p0; F21 += pz * p1; F22 += pz * p2;
        }
        float Ic = F00*F00 + F01*F01 + F02*F02
                 + F10*F10 + F11*F11 + F12*F12
                 + F20*F20 + F21*F21 + F22*F22;
        float J = F00 * (F11 * F22 - F12 * F21)
                - F01 * (F10 * F22 - F12 * F20)
                + F02 * (F10 * F21 - F11 * F20);
        float l = lam[e], m = mu[e];
        float alpha = 0.75f * m / l + 1.0f;
        float Icv = fmaxf(Ic + 1.0f, 0.0f);
        float d = J - alpha;
        float psi = 0.5f * m * (Ic - 3.0f)
                  + 0.5f * l * d * d
                  - 0.5f * m * logf(Icv + 1e-30f);
        val = psi * measure[(size_t)e * 4 + 3];
    }

#pragma unroll
    for (int off = 16; off > 0; off >>= 1)
        val += __shfl_down_sync(0xFFFFFFFFu, val, off);
    __shared__ float sh[8];
    int lane = threadIdx.x & 31;
    int warp = threadIdx.x >> 5;
    if (lane == 0) sh[warp] = val;
    __syncthreads();
    if (threadIdx.x == 0) {
        float s = 0.f;
#pragma unroll
        for (int w = 0; w < 8; ++w) s += sh[w];
        atomicAdd(&g_el_accum, (double)s);
    }
}

// ---------------------------------------------------------------------------
// Kernel 2: matvec via cp.async smem staging.
// 4 rows x 8192 cols per block, grid 2048. M is double-buffered through
// shared memory with cp.async.cg (bypasses L1; zero register staging), so
// live registers ~= 12 accums + delta(12) + addressing -> fits
// __launch_bounds__(256, 7): 1036 resident blocks, 2048/1036 = 1.98 waves
// (98.8% fill) vs 2.77 waves at 5/SM. Each thread reads back only the 16B
// chunks it staged, so cp.async.wait_group is thread-local: NO __syncthreads
// in the streaming loop (R12 lesson). Delta arrays stay L1-resident.
// ---------------------------------------------------------------------------
#define CP_ASYNC_16(saddr, gptr) \
    asm volatile("cp.async.cg.shared.global [%0], [%1], 16;" \
                 :: "r"(saddr), "l"(gptr))

__global__ __launch_bounds__(256, 7) void matvec_kernel(const float* __restrict__ M,
                                                        const float* __restrict__ ts_ptr,
                                                        float* __restrict__ out)
{
    __shared__ __align__(16) float4 smq[2][ROWS_PER_TILE][256];
    __shared__ double shd[8];

    const int t = threadIdx.x;
    const int row0 = blockIdx.x * ROWS_PER_TILE;
    const float4* __restrict__ M0 = reinterpret_cast<const float4*>(M + (size_t)(row0 + 0) * V);
    const float4* __restrict__ M1 = reinterpret_cast<const float4*>(M + (size_t)(row0 + 1) * V);
    const float4* __restrict__ M2 = reinterpret_cast<const float4*>(M + (size_t)(row0 + 2) * V);
    const float4* __restrict__ M3 = reinterpret_cast<const float4*>(M + (size_t)(row0 + 3) * V);
    const float4* __restrict__ DX = reinterpret_cast<const float4*>(g_dx);
    const float4* __restrict__ DY = reinterpret_cast<const float4*>(g_dy);
    const float4* __restrict__ DZ = reinterpret_cast<const float4*>(g_dz);

    uint32_t s0 = (uint32_t)__cvta_generic_to_shared(&smq[0][0][t]);
    uint32_t s1 = (uint32_t)__cvta_generic_to_shared(&smq[0][1][t]);
    uint32_t s2 = (uint32_t)__cvta_generic_to_shared(&smq[0][2][t]);
    uint32_t s3 = (uint32_t)__cvta_generic_to_shared(&smq[0][3][t]);
    const uint32_t BUFB = (uint32_t)(ROWS_PER_TILE * 256 * sizeof(float4)); // 16KB

    // prologue: stage chunk 0 into buffer 0
    CP_ASYNC_16(s0, &M0[t]);
    CP_ASYNC_16(s1, &M1[t]);
    CP_ASYNC_16(s2, &M2[t]);
    CP_ASYNC_16(s3, &M3[t]);
    asm volatile("cp.async.commit_group;");

    float a00=0.f,a01=0.f,a02=0.f, a10=0.f,a11=0.f,a12=0.f;
    float a20=0.f,a21=0.f,a22=0.f, a30=0.f,a31=0.f,a32=0.f;

#pragma unroll
    for (int it = 0; it < MV_ITERS; ++it) {
        // stage next chunk into the other buffer
        if (it + 1 < MV_ITERS) {
            int nidx = (it + 1) * 256 + t;
            uint32_t boff = ((it + 1) & 1) ? BUFB : 0u;
            CP_ASYNC_16(s0 + boff, &M0[nidx]);
            CP_ASYNC_16(s1 + boff, &M1[nidx]);
            CP_ASYNC_16(s2 + boff, &M2[nidx]);
            CP_ASYNC_16(s3 + boff, &M3[nidx]);
            asm volatile("cp.async.commit_group;");
            asm volatile("cp.async.wait_group 1;" ::: "memory");
        } else {
            asm volatile("cp.async.wait_group 0;" ::: "memory");
        }

        int idx = it * 256 + t;
        float4 x = DX[idx];
        float4 y = DY[idx];
        float4 z = DZ[idx];
        int buf = it & 1;
        float4 m0 = smq[buf][0][t];
        float4 m1 = smq[buf][1][t];
        float4 m2 = smq[buf][2][t];
        float4 m3 = smq[buf][3][t];

        a00 += m0.x*x.x + m0.y*x.y + m0.z*x.z + m0.w*x.w;
        a01 += m0.x*y.x + m0.y*y.y + m0.z*y.z + m0.w*y.w;
        a02 += m0.x*z.x + m0.y*z.y + m0.z*z.z + m0.w*z.w;

        a10 += m1.x*x.x + m1.y*x.y + m1.z*x.z + m1.w*x.w;
        a11 += m1.x*y.x + m1.y*y.y + m1.z*y.z + m1.w*y.w;
        a12 += m1.x*z.x + m1.y*z.y + m1.z*z.z + m1.w*z.w;

        a20 += m2.x*x.x + m2.y*x.y + m2.z*x.z + m2.w*x.w;
        a21 += m2.x*y.x + m2.y*y.y + m2.z*y.z + m2.w*y.w;
        a22 += m2.x*z.x + m2.y*z.y + m2.z*z.z + m2.w*z.w;

        a30 += m3.x*x.x + m3.y*x.y + m3.z*x.z + m3.w*x.w;
        a31 += m3.x*y.x + m3.y*y.y + m3.z*y.z + m3.w*y.w;
        a32 += m3.x*z.x + m3.y*z.y + m3.z*z.z + m3.w*z.w;
    }

    // fold the delta[row] weights per-thread (broadcast L1 loads), then one
    // double reduction + one atomic per block.
    double tacc = (double)( g_dx[row0 + 0] * a00 + g_dy[row0 + 0] * a01 + g_dz[row0 + 0] * a02
                          + g_dx[row0 + 1] * a10 + g_dy[row0 + 1] * a11 + g_dz[row0 + 1] * a12
                          + g_dx[row0 + 2] * a20 + g_dy[row0 + 2] * a21 + g_dz[row0 + 2] * a22
                          + g_dx[row0 + 3] * a30 + g_dy[row0 + 3] * a31 + g_dz[row0 + 3] * a32 );

#pragma unroll
    for (int off = 16; off > 0; off >>= 1)
        tacc += __shfl_down_sync(0xFFFFFFFFu, tacc, off);
    int lane = threadIdx.x & 31;
    int warp = threadIdx.x >> 5;
    if (lane == 0) shd[warp] = tacc;
    __syncthreads();

    if (threadIdx.x == 0) {
        double s = 0.0;
#pragma unroll
        for (int w = 0; w < 8; ++w) s += shd[w];
        atomicAdd(&g_kin_accum, s);

        __threadfence();
        unsigned int done = atomicAdd(&g_done, 1u);
        if (done == (unsigned int)(MV_BLOCKS - 1)) {
            // all kinetic atomics visible; elastic finished (stream order)
            double dt = (double)ts_ptr[0];
            double inv_h = 1.0 / dt;
            double coeff = inv_h * inv_h * 0.5;
            double kin = coeff * g_kin_accum;
            double el  = g_el_accum;
            out[0] = (float)(kin + el);
            out[1] = (float)kin;
            out[2] = (float)el;
        }
    }
}

// ---------------------------------------------------------------------------
// Launch
// ---------------------------------------------------------------------------
extern "C" void kernel_launch(void* const* d_in, const int* in_sizes, int n_in,
                              void* d_out, int out_size)
{
    const float* next_pos = (const float*)d_in[0];
    const float* pos      = (const float*)d_in[1];
    const float* vel      = (const float*)d_in[2];
    const float* ext      = (const float*)d_in[3];
    const float* M        = (const float*)d_in[4];
    const int*   elems    = (const int*)d_in[5];
    const float* poly     = (const float*)d_in[6];
    const float* measure  = (const float*)d_in[7];
    const float* lam      = (const float*)d_in[8];
    const float* mu       = (const float*)d_in[9];
    const float* ts       = (const float*)d_in[10];
    float* out = (float*)d_out;

    prologue_kernel<<<E_BLOCKS, 256>>>(next_pos, pos, vel, ext, ts,
                                       elems, poly, measure, lam, mu);
    matvec_kernel<<<MV_BLOCKS, 256>>>(M, ts, out);
}

// round 14
// speedup vs baseline: 1.2981x; 1.2981x over previous
#include <cuda_runtime.h>
#include <cstdint>

// Problem constants (fixed by the dataset: V=8192 vertices, E=40000 tets)
#define V 8192
#define E 40000
#define ROWS_PER_TILE 4
#define MV_TILES (V / ROWS_PER_TILE)          // 2048 matvec tiles
#define EL_BLOCKS ((E + 255) / 256)           // 157 elastic blocks
#define TOTAL_BLOCKS (MV_TILES + EL_BLOCKS)   // 2205

// Scratch (device globals — no allocations allowed). 16B-aligned for float4 LDG.
__device__ __align__(16) float g_dx[V];
__device__ __align__(16) float g_dy[V];
__device__ __align__(16) float g_dz[V];
__device__ double g_kin_accum;    // sum_i delta_i . (M delta)_i   (atomic)
__device__ double g_el_accum;     // sum_e psi_e * measure_e       (atomic)
__device__ unsigned int g_done;   // completion counter (all TOTAL_BLOCKS)

// ---------------------------------------------------------------------------
// Kernel 1: delta = next_position - (position + velocity*dt + ext_acc*dt^2)
// (SoA for float4 loads). Thread 0 resets accumulators (stream-ordered
// before kernel 2). Tiny: 32 blocks.
// ---------------------------------------------------------------------------
__global__ void delta_kernel(const float* __restrict__ next_pos,
                             const float* __restrict__ pos,
                             const float* __restrict__ vel,
                             const float* __restrict__ ext,
                             const float* __restrict__ ts_ptr)
{
    int v = blockIdx.x * blockDim.x + threadIdx.x;
    if (v == 0) {
        g_kin_accum = 0.0;
        g_el_accum  = 0.0;
        g_done      = 0u;
    }
    if (v >= V) return;
    float dt  = ts_ptr[0];
    float dt2 = dt * dt;
    int b = v * 3;
    g_dx[v] = next_pos[b + 0] - (pos[b + 0] + vel[b + 0] * dt + ext[b + 0] * dt2);
    g_dy[v] = next_pos[b + 1] - (pos[b + 1] + vel[b + 1] * dt + ext[b + 1] * dt2);
    g_dz[v] = next_pos[b + 2] - (pos[b + 2] + vel[b + 2] * dt + ext[b + 2] * dt2);
}

// ---------------------------------------------------------------------------
// Kernel 2 (mega): blocks [0, 2048) = matvec tiles (exact R11 best-measured
// shape: 4 rows x 8192 cols, plain 7-LDG/48-FFMA loop, __ldcs on M,
// 5 blocks/SM); blocks [2048, 2205) = elastic element blocks, appended at
// the END of the bid range so the FIFO scheduler packs them into the
// under-filled (77%) final matvec wave — near-free execution.
// Every block bumps g_done after its atomic; the last of all 2205 blocks
// writes the 3 outputs.
// elements is int32 on device (JAX x64 disabled); clamped defensively.
// ---------------------------------------------------------------------------
__global__ __launch_bounds__(256, 5) void mega_kernel(
    const float* __restrict__ M,
    const float* __restrict__ next_pos,
    const int* __restrict__ elems,
    const float* __restrict__ poly,
    const float* __restrict__ measure,
    const float* __restrict__ lam,
    const float* __restrict__ mu,
    const float* __restrict__ ts_ptr,
    float* __restrict__ out)
{
    const int bid = blockIdx.x;

    if (bid < MV_TILES) {
        // ------------------------- matvec tile path -------------------------
        const int row0 = bid * ROWS_PER_TILE;
        const float4* __restrict__ M0 = reinterpret_cast<const float4*>(M + (size_t)(row0 + 0) * V);
        const float4* __restrict__ M1 = reinterpret_cast<const float4*>(M + (size_t)(row0 + 1) * V);
        const float4* __restrict__ M2 = reinterpret_cast<const float4*>(M + (size_t)(row0 + 2) * V);
        const float4* __restrict__ M3 = reinterpret_cast<const float4*>(M + (size_t)(row0 + 3) * V);
        const float4* __restrict__ DX = reinterpret_cast<const float4*>(g_dx);
        const float4* __restrict__ DY = reinterpret_cast<const float4*>(g_dy);
        const float4* __restrict__ DZ = reinterpret_cast<const float4*>(g_dz);

        float a00=0.f,a01=0.f,a02=0.f, a10=0.f,a11=0.f,a12=0.f;
        float a20=0.f,a21=0.f,a22=0.f, a30=0.f,a31=0.f,a32=0.f;

#pragma unroll
        for (int it = 0; it < (V / 4) / 256; ++it) {
            int idx = threadIdx.x + it * 256;
            float4 m0 = __ldcs(&M0[idx]);
            float4 m1 = __ldcs(&M1[idx]);
            float4 m2 = __ldcs(&M2[idx]);
            float4 m3 = __ldcs(&M3[idx]);
            float4 x  = DX[idx];
            float4 y  = DY[idx];
            float4 z  = DZ[idx];

            a00 += m0.x*x.x + m0.y*x.y + m0.z*x.z + m0.w*x.w;
            a01 += m0.x*y.x + m0.y*y.y + m0.z*y.z + m0.w*y.w;
            a02 += m0.x*z.x + m0.y*z.y + m0.z*z.z + m0.w*z.w;

            a10 += m1.x*x.x + m1.y*x.y + m1.z*x.z + m1.w*x.w;
            a11 += m1.x*y.x + m1.y*y.y + m1.z*y.z + m1.w*y.w;
            a12 += m1.x*z.x + m1.y*z.y + m1.z*z.z + m1.w*z.w;

            a20 += m2.x*x.x + m2.y*x.y + m2.z*x.z + m2.w*x.w;
            a21 += m2.x*y.x + m2.y*y.y + m2.z*y.z + m2.w*y.w;
            a22 += m2.x*z.x + m2.y*z.y + m2.z*z.z + m2.w*z.w;

            a30 += m3.x*x.x + m3.y*x.y + m3.z*x.z + m3.w*x.w;
            a31 += m3.x*y.x + m3.y*y.y + m3.z*y.z + m3.w*y.w;
            a32 += m3.x*z.x + m3.y*z.y + m3.z*z.z + m3.w*z.w;
        }

        // reduce 12 partials: warp shuffles then smem
#pragma unroll
        for (int off = 16; off > 0; off >>= 1) {
            a00 += __shfl_down_sync(0xFFFFFFFFu, a00, off);
            a01 += __shfl_down_sync(0xFFFFFFFFu, a01, off);
            a02 += __shfl_down_sync(0xFFFFFFFFu, a02, off);
            a10 += __shfl_down_sync(0xFFFFFFFFu, a10, off);
            a11 += __shfl_down_sync(0xFFFFFFFFu, a11, off);
            a12 += __shfl_down_sync(0xFFFFFFFFu, a12, off);
            a20 += __shfl_down_sync(0xFFFFFFFFu, a20, off);
            a21 += __shfl_down_sync(0xFFFFFFFFu, a21, off);
            a22 += __shfl_down_sync(0xFFFFFFFFu, a22, off);
            a30 += __shfl_down_sync(0xFFFFFFFFu, a30, off);
            a31 += __shfl_down_sync(0xFFFFFFFFu, a31, off);
            a32 += __shfl_down_sync(0xFFFFFFFFu, a32, off);
        }
        __shared__ float sh[12][8];
        int lane = threadIdx.x & 31;
        int warp = threadIdx.x >> 5;
        if (lane == 0) {
            sh[0][warp]=a00; sh[1][warp]=a01; sh[2][warp]=a02;
            sh[3][warp]=a10; sh[4][warp]=a11; sh[5][warp]=a12;
            sh[6][warp]=a20; sh[7][warp]=a21; sh[8][warp]=a22;
            sh[9][warp]=a30; sh[10][warp]=a31; sh[11][warp]=a32;
        }
        __syncthreads();

        if (threadIdx.x < 12) {
            float s = 0.f;
#pragma unroll
            for (int w = 0; w < 8; ++w) s += sh[threadIdx.x][w];
            sh[threadIdx.x][0] = s;
        }
        __syncthreads();

        if (threadIdx.x == 0) {
            double contrib = 0.0;
#pragma unroll
            for (int r = 0; r < ROWS_PER_TILE; ++r) {
                int row = row0 + r;
                contrib += (double)g_dx[row] * sh[r*3+0][0]
                         + (double)g_dy[row] * sh[r*3+1][0]
                         + (double)g_dz[row] * sh[r*3+2][0];
            }
            atomicAdd(&g_kin_accum, contrib);
        }
    } else {
        // -------------------------- elastic path ---------------------------
        int e = (bid - MV_TILES) * 256 + threadIdx.x;
        float val = 0.f;
        if (e < E) {
            float F00 = 0.f, F01 = 0.f, F02 = 0.f;
            float F10 = 0.f, F11 = 0.f, F12 = 0.f;
            float F20 = 0.f, F21 = 0.f, F22 = 0.f;
            const int4 ev = reinterpret_cast<const int4*>(elems)[e];
            int vidx[4] = { ev.x, ev.y, ev.z, ev.w };
            const float4* __restrict__ pl4 = reinterpret_cast<const float4*>(poly) + (size_t)e * 4;
#pragma unroll
            for (int f = 0; f < 4; ++f) {
                int vi = vidx[f];
                vi = vi < 0 ? 0 : (vi >= V ? V - 1 : vi);   // defensive clamp
                const float* p = next_pos + (size_t)vi * 3;
                float px = p[0], py = p[1], pz = p[2];
                float4 pl = pl4[f];
                float p0 = pl.x, p1 = pl.y, p2 = pl.z;
                F00 += px * p0; F01 += px * p1; F02 += px * p2;
                F10 += py * p0; F11 += py * p1; F12 += py * p2;
                F20 += pz * p0; F21 += pz * p1; F22 += pz * p2;
            }
            float Ic = F00*F00 + F01*F01 + F02*F02
                     + F10*F10 + F11*F11 + F12*F12
                     + F20*F20 + F21*F21 + F22*F22;
            float J = F00 * (F11 * F22 - F12 * F21)
                    - F01 * (F10 * F22 - F12 * F20)
                    + F02 * (F10 * F21 - F11 * F20);
            float l = lam[e], m = mu[e];
            float alpha = 0.75f * m / l + 1.0f;
            float Icv = fmaxf(Ic + 1.0f, 0.0f);
            float d = J - alpha;
            float psi = 0.5f * m * (Ic - 3.0f)
                      + 0.5f * l * d * d
                      - 0.5f * m * logf(Icv + 1e-30f);
            val = psi * measure[(size_t)e * 4 + 3];
        }

#pragma unroll
        for (int off = 16; off > 0; off >>= 1)
            val += __shfl_down_sync(0xFFFFFFFFu, val, off);
        __shared__ float she[8];
        int lane = threadIdx.x & 31;
        int warp = threadIdx.x >> 5;
        if (lane == 0) she[warp] = val;
        __syncthreads();
        if (threadIdx.x == 0) {
            float s = 0.f;
#pragma unroll
            for (int w = 0; w < 8; ++w) s += she[w];
            atomicAdd(&g_el_accum, (double)s);
        }
    }

    // ---------------- completion ticket + final output write ----------------
    if (threadIdx.x == 0) {
        __threadfence();
        unsigned int t = atomicAdd(&g_done, 1u);
        if (t == (unsigned int)(TOTAL_BLOCKS - 1)) {
            __threadfence();
            double dt = (double)ts_ptr[0];
            double inv_h = 1.0 / dt;
            double coeff = inv_h * inv_h * 0.5;
            double kin = coeff * g_kin_accum;
            double el  = g_el_accum;
            out[0] = (float)(kin + el);
            out[1] = (float)kin;
            out[2] = (float)el;
        }
    }
}

// ---------------------------------------------------------------------------
// Launch
// ---------------------------------------------------------------------------
extern "C" void kernel_launch(void* const* d_in, const int* in_sizes, int n_in,
                              void* d_out, int out_size)
{
    const float* next_pos = (const float*)d_in[0];
    const float* pos      = (const float*)d_in[1];
    const float* vel      = (const float*)d_in[2];
    const float* ext      = (const float*)d_in[3];
    const float* M        = (const float*)d_in[4];
    const int*   elems    = (const int*)d_in[5];
    const float* poly     = (const float*)d_in[6];
    const float* measure  = (const float*)d_in[7];
    const float* lam      = (const float*)d_in[8];
    const float* mu       = (const float*)d_in[9];
    const float* ts       = (const float*)d_in[10];
    float* out = (float*)d_out;

    delta_kernel<<<(V + 255) / 256, 256>>>(next_pos, pos, vel, ext, ts);
    mega_kernel<<<TOTAL_BLOCKS, 256>>>(M, next_pos, elems, poly, measure,
                                       lam, mu, ts, out);
}